// round 14
// baseline (speedup 1.0000x reference)
#include <cuda_runtime.h>
#include <cuda_fp16.h>
#include <cstdint>

// ---------------- problem constants ----------------
#define MD   4096
#define KD   4096
#define BSD  8192
#define NTOT 16777216ull
#define NLUT 262144              // 2^18 intervals; d index = d/64 exactly

// ---------------- scratch (device globals) ----------------
__device__ __half  g_wh[(size_t)MD * KD];
__device__ __half  g_xh[(size_t)BSD * KD];
__device__ float   g_lut[NLUT + 1];
__device__ double2 g_part[64];
__device__ float   g_stats[2];
__device__ int     g_counter;

// ---------------- 0) build r(ang) LUT ----------------
__global__ void __launch_bounds__(256) lut_kernel(const float* __restrict__ dna) {
    int i = blockIdx.x * blockDim.x + threadIdx.x;
    if (i > NLUT) return;
    float mp = dna[0], a = dna[1], b = dna[2], n1 = dna[3], n2 = dna[4], n3 = dna[5];
    float span = mp * 2.0f * 3.14159265358979323846f * 0.25f;
    float ang = span * ((float)i / (float)NLUT);
    float sn, cs; sincosf(ang, &sn, &cs);
    float bse = powf(fabsf(cs / a), n2) + powf(fabsf(sn / b), n3);
    g_lut[i] = powf(bse, -1.0f / n1);
}

__device__ __forceinline__ float lut_r(int d) {
    float u = (float)d * (1.0f / 64.0f);
    int i = (int)u;
    i = i < NLUT ? i : NLUT - 1;
    float f = u - (float)i;
    float v0 = g_lut[i], v1 = g_lut[i + 1];
    return v0 + f * (v1 - v0);
}

// ---------------- 1) closed-form stats from LUT ----------------
__global__ void __launch_bounds__(256) stat_kernel() {
    __shared__ double s1[256], s2[256];
    __shared__ int lastFlag;
    int t = threadIdx.x;
    double s = 0.0, q = 0.0;
    int base = blockIdx.x * (NLUT / 64);
    for (int j = t; j < NLUT / 64; j += 256) {
        int i = base + j;
        double v0 = (double)g_lut[i];
        double dv = (double)g_lut[i + 1] - v0;
        s += 64.0 * v0 + 31.5 * dv;
        q += 64.0 * v0 * v0 + 63.0 * v0 * dv + 20.8359375 * dv * dv;
    }
    s1[t] = s; s2[t] = q; __syncthreads();
    for (int o = 128; o > 0; o >>= 1) {
        if (t < o) { s1[t] += s1[t + o]; s2[t] += s2[t + o]; }
        __syncthreads();
    }
    if (t == 0) {
        double2 p; p.x = s1[0]; p.y = s2[0];
        g_part[blockIdx.x] = p;
        __threadfence();
        int old = atomicAdd(&g_counter, 1);
        lastFlag = (old == gridDim.x - 1) ? 1 : 0;
    }
    __syncthreads();
    if (lastFlag) {
        __threadfence();
        double fs = 0.0, fq = 0.0;
        if (t < 64) { double2 p = g_part[t]; fs = p.x; fq = p.y; }
        s1[t] = fs; s2[t] = fq; __syncthreads();
        for (int o = 128; o > 0; o >>= 1) {
            if (t < o) { s1[t] += s1[t + o]; s2[t] += s2[t + o]; }
            __syncthreads();
        }
        if (t == 0) {
            double N = (double)NTOT;
            double mean = s1[0] / N;
            double var  = (s2[0] - s1[0] * s1[0] / N) / (N - 1.0);
            double alpha = (1.0 / 64.0) / (sqrt(var) + 1e-9);
            g_stats[0] = (float)mean;
            g_stats[1] = (float)alpha;
            g_counter = 0;
        }
    }
}

// ---------------- 2) fused prep: w' (blocks 0..8191), x (8192..12287) -------
__global__ void __launch_bounds__(256) prep_kernel(const int* __restrict__ hd,
                                                   const float* __restrict__ x) {
    int t = threadIdx.x;
    if (blockIdx.x < 8192) {
        float mean = g_stats[0], al = g_stats[1];
        size_t base = (size_t)blockIdx.x * 2048;
#pragma unroll
        for (int j = 0; j < 8; j++) {
            size_t i = base + (size_t)j * 256 + t;
            float r = lut_r(hd[i]);
            g_wh[i] = __float2half_rn((r - mean) * al);
        }
    } else {
        const float4* xi = reinterpret_cast<const float4*>(x);
        uint2* xo = reinterpret_cast<uint2*>(g_xh);
        size_t base = (size_t)(blockIdx.x - 8192) * 2048;
#pragma unroll
        for (int j = 0; j < 8; j++) {
            size_t i = base + (size_t)j * 256 + t;
            float4 v = xi[i];
            __half2 h0 = __floats2half2_rn(v.x, v.y);
            __half2 h1 = __floats2half2_rn(v.z, v.w);
            uint2 o;
            o.x = *reinterpret_cast<uint32_t*>(&h0);
            o.y = *reinterpret_cast<uint32_t*>(&h1);
            xo[i] = o;
        }
    }
}

// --- 3) FP16 GEMM: mbarrier pipeline, 2 CTAs/SM, 128 thr, 4 warps of 64x64 ---
#define BM 128
#define BN 128
#define BK 64
#define KCH (KD / BK)              // 64
#define STAGES 3
#define AW 72                      // 64 + 8 pad halfs -> 144B row stride
#define A_HALFS (BM * AW)
#define B_HALFS (BN * AW)
#define STAGE_HALFS (A_HALFS + B_HALFS)        // 18432
#define STAGE_BYTES (STAGE_HALFS * 2)          // 36864
#define MBAR_OFF (STAGES * STAGE_BYTES)        // 110592
#define SMEM_TOTAL (MBAR_OFF + 64)             // 110656 per CTA

__device__ __forceinline__ void cp16(uint32_t saddr, const void* gaddr) {
    asm volatile("cp.async.cg.shared.global [%0], [%1], 16;" :: "r"(saddr), "l"(gaddr));
}
__device__ __forceinline__ void cp_arrive(uint32_t mbar) {
    asm volatile("cp.async.mbarrier.arrive.noinc.shared.b64 [%0];" :: "r"(mbar) : "memory");
}
__device__ __forceinline__ void mbar_init(uint32_t mbar, uint32_t cnt) {
    asm volatile("mbarrier.init.shared.b64 [%0], %1;" :: "r"(mbar), "r"(cnt) : "memory");
}
__device__ __forceinline__ void mbar_arrive(uint32_t mbar) {
    asm volatile("mbarrier.arrive.shared.b64 _, [%0];" :: "r"(mbar) : "memory");
}
__device__ __forceinline__ void mbar_wait(uint32_t mbar, uint32_t par) {
    uint32_t done;
    asm volatile("{\n\t.reg .pred p;\n\t"
                 "mbarrier.try_wait.parity.acquire.cta.shared::cta.b64 p, [%1], %2;\n\t"
                 "selp.b32 %0,1,0,p;\n\t}"
                 : "=r"(done) : "r"(mbar), "r"(par) : "memory");
    if (!done) {
        asm volatile("{\n\t.reg .pred P1;\n\t"
                     "WL_%=:\n\t"
                     "mbarrier.try_wait.parity.acquire.cta.shared::cta.b64 P1, [%0], %1, 0x989680;\n\t"
                     "@P1 bra.uni WD_%=;\n\t"
                     "bra.uni WL_%=;\n\t"
                     "WD_%=:\n\t}"
                     :: "r"(mbar), "r"(par) : "memory");
    }
}
__device__ __forceinline__ void ldsm4(uint32_t& r0, uint32_t& r1, uint32_t& r2, uint32_t& r3,
                                      uint32_t addr) {
    asm volatile("ldmatrix.sync.aligned.m8n8.x4.shared.b16 {%0,%1,%2,%3}, [%4];"
                 : "=r"(r0), "=r"(r1), "=r"(r2), "=r"(r3) : "r"(addr));
}
__device__ __forceinline__ void mma_f16(float* d, const uint32_t* a, const uint32_t* b) {
    asm volatile("mma.sync.aligned.m16n8k16.row.col.f32.f16.f16.f32 "
                 "{%0,%1,%2,%3}, {%4,%5,%6,%7}, {%8,%9}, {%0,%1,%2,%3};"
                 : "+f"(d[0]), "+f"(d[1]), "+f"(d[2]), "+f"(d[3])
                 : "r"(a[0]), "r"(a[1]), "r"(a[2]), "r"(a[3]), "r"(b[0]), "r"(b[1]));
}

__global__ void __launch_bounds__(128, 2) gemm_f16(const float* __restrict__ bias,
                                                   float* __restrict__ out) {
    extern __shared__ __half smh[];
    uint32_t smbase = (uint32_t)__cvta_generic_to_shared(smh);
    uint32_t mbFull  = smbase + MBAR_OFF;        // 3 x 8B
    uint32_t mbEmpty = smbase + MBAR_OFF + 24;   // 3 x 8B
    int tid = threadIdx.x, wid = tid >> 5, lane = tid & 31;
    int wr = wid & 1;            // 2 bs-groups of 64
    int wc = wid >> 1;           // 2 m-groups of 64
    int g = lane >> 2, tig = lane & 3;
    int mBase  = blockIdx.x * BN;
    int bsBase = blockIdx.y * BM;

    if (tid == 0) {
#pragma unroll
        for (int s = 0; s < STAGES; s++) {
            mbar_init(mbFull  + s * 8, 128);  // cp-tracked: every thread arrives
            mbar_init(mbEmpty + s * 8, 4);    // one arrival per warp
        }
    }
    __syncthreads();

    // cp.async staging: srow 0..15, sseg 0..7; rows covered via j*16 (8 groups each)
    int srow = tid >> 3, sseg = tid & 7;
    const __half* gA = g_xh + (size_t)(bsBase + srow) * KD + sseg * 8;
    const __half* gB = g_wh + (size_t)(mBase  + srow) * KD + sseg * 8;
    uint32_t sA0 = smbase + (uint32_t)((srow * AW + sseg * 8) * 2);
    uint32_t sB0 = smbase + (uint32_t)((A_HALFS + srow * AW + sseg * 8) * 2);

    // 4 cp16s (2 A-rows + 2 B-rows), quarter q of stage slot
#define ISSUE_QTR(slot, cc, q)                                                         \
    do {                                                                               \
        uint32_t so = (uint32_t)((slot) * STAGE_BYTES);                                \
        cp16(sA0 + so + ((q) * 2 + 0) * 16 * AW * 2,                                   \
             gA + (cc) * BK + (size_t)((q) * 2 + 0) * 16 * KD);                        \
        cp16(sA0 + so + ((q) * 2 + 1) * 16 * AW * 2,                                   \
             gA + (cc) * BK + (size_t)((q) * 2 + 1) * 16 * KD);                        \
        cp16(sB0 + so + ((q) * 2 + 0) * 16 * AW * 2,                                   \
             gB + (cc) * BK + (size_t)((q) * 2 + 0) * 16 * KD);                        \
        cp16(sB0 + so + ((q) * 2 + 1) * 16 * AW * 2,                                   \
             gB + (cc) * BK + (size_t)((q) * 2 + 1) * 16 * KD);                        \
    } while (0)

#define ISSUE_STAGE(slot, cc)                                                          \
    do {                                                                               \
        ISSUE_QTR(slot, cc, 0); ISSUE_QTR(slot, cc, 1);                                \
        ISSUE_QTR(slot, cc, 2); ISSUE_QTR(slot, cc, 3);                                \
        cp_arrive(mbFull + (slot) * 8);                                                \
    } while (0)

    // prologue: fill stages 0,1 (chunks 0,1)
    ISSUE_STAGE(0, 0);
    ISSUE_STAGE(1, 1);

    // ldmatrix lane addressing
    int li = lane & 7, qq = lane >> 3;
    uint32_t aAddr[4], bAddr[4];
#pragma unroll
    for (int mt = 0; mt < 4; mt++) {
        int row = wr * 64 + mt * 16 + (qq & 1) * 8 + li;
        aAddr[mt] = smbase + (uint32_t)((row * AW + (qq >> 1) * 8) * 2);
    }
#pragma unroll
    for (int p = 0; p < 4; p++) {
        int row = wc * 64 + p * 16 + (qq >> 1) * 8 + li;
        bAddr[p] = smbase + (uint32_t)((A_HALFS + row * AW + (qq & 1) * 8) * 2);
    }

    float acc[4][8][4];
#pragma unroll
    for (int mt = 0; mt < 4; mt++)
#pragma unroll
        for (int nt = 0; nt < 8; nt++)
#pragma unroll
            for (int v = 0; v < 4; v++) acc[mt][nt][v] = 0.0f;

    uint32_t af0[4][4], bf0[8][2], af1[4][4], bf1[8][2];

#define LOADF(AF, BF, kb)                                                              \
    do {                                                                               \
        _Pragma("unroll")                                                              \
        for (int mt = 0; mt < 4; mt++)                                                 \
            ldsm4(AF[mt][0], AF[mt][1], AF[mt][2], AF[mt][3], aAddr[mt] + (kb));       \
        _Pragma("unroll")                                                              \
        for (int p = 0; p < 4; p++) {                                                  \
            uint32_t r0, r1, r2, r3;                                                   \
            ldsm4(r0, r1, r2, r3, bAddr[p] + (kb));                                    \
            BF[2 * p][0] = r0;     BF[2 * p][1] = r1;                                  \
            BF[2 * p + 1][0] = r2; BF[2 * p + 1][1] = r3;                              \
        }                                                                              \
    } while (0)

#define MMAB(AF, BF)                                                                   \
    do {                                                                               \
        _Pragma("unroll")                                                              \
        for (int mt = 0; mt < 4; mt++)                                                 \
            _Pragma("unroll")                                                          \
            for (int nt = 0; nt < 8; nt++)                                             \
                mma_f16(acc[mt][nt], AF[mt], BF[nt]);                                  \
    } while (0)

    for (int c = 0; c < KCH; c++) {
        int s = c % STAGES;
        int cd3 = c / STAGES;
        mbar_wait(mbFull + s * 8, (uint32_t)(cd3 & 1));

        int c2 = c + 2;
        int s2 = c2 % STAGES;
        bool doIssue = (c2 < KCH);
        if (doIssue && c2 >= STAGES)
            mbar_wait(mbEmpty + s2 * 8, (uint32_t)((c2 / STAGES + 1) & 1));

        uint32_t st = (uint32_t)(s * STAGE_BYTES);
        // fragment double-buffer across ks, cp16s spread through the loop
        LOADF(af0, bf0, st);                 // ks0
        LOADF(af1, bf1, st + 32);            // ks1
        if (doIssue) ISSUE_QTR(s2, c2, 0);
        MMAB(af0, bf0);                      // ks0 MMAs
        LOADF(af0, bf0, st + 64);            // ks2
        if (doIssue) ISSUE_QTR(s2, c2, 1);
        MMAB(af1, bf1);                      // ks1 MMAs
        LOADF(af1, bf1, st + 96);            // ks3
        if (doIssue) ISSUE_QTR(s2, c2, 2);
        MMAB(af0, bf0);                      // ks2 MMAs
        if (doIssue) { ISSUE_QTR(s2, c2, 3); cp_arrive(mbFull + s2 * 8); }
        MMAB(af1, bf1);                      // ks3 MMAs

        if (lane == 0) mbar_arrive(mbEmpty + s * 8);   // warp-level arrival (count 4)
    }

    __syncthreads();
#pragma unroll
    for (int nt = 0; nt < 8; nt++) {
        int col = mBase + wc * 64 + nt * 8 + 2 * tig;
        float2 bv = *reinterpret_cast<const float2*>(bias + col);
#pragma unroll
        for (int mt = 0; mt < 4; mt++) {
            int r0 = bsBase + wr * 64 + mt * 16 + g;
            float2 o0, o1;
            o0.x = acc[mt][nt][0] + bv.x;
            o0.y = acc[mt][nt][1] + bv.y;
            o1.x = acc[mt][nt][2] + bv.x;
            o1.y = acc[mt][nt][3] + bv.y;
            *reinterpret_cast<float2*>(out + (size_t)r0 * MD + col) = o0;
            *reinterpret_cast<float2*>(out + (size_t)(r0 + 8) * MD + col) = o1;
        }
    }
}

// ---------------- launch ----------------
extern "C" void kernel_launch(void* const* d_in, const int* in_sizes, int n_in,
                              void* d_out, int out_size) {
    const float* x    = (const float*)d_in[0];
    const float* dna  = (const float*)d_in[1];
    const float* bias = (const float*)d_in[2];
    const int*   hd   = (const int*)d_in[3];

    lut_kernel<<<(NLUT + 1 + 255) / 256, 256>>>(dna);
    stat_kernel<<<64, 256>>>();
    prep_kernel<<<12288, 256>>>(hd, x);

    cudaFuncSetAttribute(gemm_f16, cudaFuncAttributeMaxDynamicSharedMemorySize, SMEM_TOTAL);
    dim3 grid(MD / BN, BSD / BM);   // (32, 64), m-fastest
    gemm_f16<<<grid, 128, SMEM_TOTAL>>>(bias, (float*)d_out);
}

// round 15
// speedup vs baseline: 1.0277x; 1.0277x over previous
#include <cuda_runtime.h>
#include <cuda_fp16.h>
#include <cstdint>

// ---------------- problem constants ----------------
#define MD   4096
#define KD   4096
#define BSD  8192
#define NTOT 16777216ull
#define NLUT 262144              // 2^18 intervals; d index = d/64 exactly

// ---------------- scratch (device globals) ----------------
__device__ __half  g_wh[(size_t)MD * KD];
__device__ __half  g_xh[(size_t)BSD * KD];
__device__ float   g_lut[NLUT + 1];
__device__ double2 g_part[64];
__device__ float   g_stats[2];
__device__ int     g_counter;

// ---------------- 0) build r(ang) LUT ----------------
__global__ void __launch_bounds__(256) lut_kernel(const float* __restrict__ dna) {
    int i = blockIdx.x * blockDim.x + threadIdx.x;
    if (i > NLUT) return;
    float mp = dna[0], a = dna[1], b = dna[2], n1 = dna[3], n2 = dna[4], n3 = dna[5];
    float span = mp * 2.0f * 3.14159265358979323846f * 0.25f;
    float ang = span * ((float)i / (float)NLUT);
    float sn, cs; sincosf(ang, &sn, &cs);
    float bse = powf(fabsf(cs / a), n2) + powf(fabsf(sn / b), n3);
    g_lut[i] = powf(bse, -1.0f / n1);
}

__device__ __forceinline__ float lut_r(int d) {
    float u = (float)d * (1.0f / 64.0f);
    int i = (int)u;
    i = i < NLUT ? i : NLUT - 1;
    float f = u - (float)i;
    float v0 = g_lut[i], v1 = g_lut[i + 1];
    return v0 + f * (v1 - v0);
}

// ---------------- 1) closed-form stats from LUT ----------------
// hilbert_d is a bijection onto [0,2^24); interval i covers d=64i..64i+63,
// f = j/64: sum_j f = 31.5, sum_j f^2 = 20.8359375.
__global__ void __launch_bounds__(256) stat_kernel() {
    __shared__ double s1[256], s2[256];
    __shared__ int lastFlag;
    int t = threadIdx.x;
    double s = 0.0, q = 0.0;
    int base = blockIdx.x * (NLUT / 64);
    for (int j = t; j < NLUT / 64; j += 256) {
        int i = base + j;
        double v0 = (double)g_lut[i];
        double dv = (double)g_lut[i + 1] - v0;
        s += 64.0 * v0 + 31.5 * dv;
        q += 64.0 * v0 * v0 + 63.0 * v0 * dv + 20.8359375 * dv * dv;
    }
    s1[t] = s; s2[t] = q; __syncthreads();
    for (int o = 128; o > 0; o >>= 1) {
        if (t < o) { s1[t] += s1[t + o]; s2[t] += s2[t + o]; }
        __syncthreads();
    }
    if (t == 0) {
        double2 p; p.x = s1[0]; p.y = s2[0];
        g_part[blockIdx.x] = p;
        __threadfence();
        int old = atomicAdd(&g_counter, 1);
        lastFlag = (old == gridDim.x - 1) ? 1 : 0;
    }
    __syncthreads();
    if (lastFlag) {
        __threadfence();
        double fs = 0.0, fq = 0.0;
        if (t < 64) { double2 p = g_part[t]; fs = p.x; fq = p.y; }
        s1[t] = fs; s2[t] = fq; __syncthreads();
        for (int o = 128; o > 0; o >>= 1) {
            if (t < o) { s1[t] += s1[t + o]; s2[t] += s2[t + o]; }
            __syncthreads();
        }
        if (t == 0) {
            double N = (double)NTOT;
            double mean = s1[0] / N;
            double var  = (s2[0] - s1[0] * s1[0] / N) / (N - 1.0);
            double alpha = (1.0 / 64.0) / (sqrt(var) + 1e-9);
            g_stats[0] = (float)mean;
            g_stats[1] = (float)alpha;
            g_counter = 0;
        }
    }
}

// ---------------- 2) fused prep: w' (blocks 0..8191), x (8192..12287) -------
// w side vectorized: int2 hd loads, __half2 stores (2 elems/thread/iter).
__global__ void __launch_bounds__(256) prep_kernel(const int* __restrict__ hd,
                                                   const float* __restrict__ x) {
    int t = threadIdx.x;
    if (blockIdx.x < 8192) {
        float mean = g_stats[0], al = g_stats[1];
        const int2* hd2 = reinterpret_cast<const int2*>(hd);
        __half2* wo = reinterpret_cast<__half2*>(g_wh);
        size_t base = (size_t)blockIdx.x * 1024;          // in half2 units (2048 halfs)
#pragma unroll
        for (int j = 0; j < 4; j++) {
            size_t i = base + (size_t)j * 256 + t;
            int2 d = hd2[i];
            float r0 = lut_r(d.x);
            float r1 = lut_r(d.y);
            wo[i] = __floats2half2_rn((r0 - mean) * al, (r1 - mean) * al);
        }
    } else {
        const float4* xi = reinterpret_cast<const float4*>(x);
        uint2* xo = reinterpret_cast<uint2*>(g_xh);
        size_t base = (size_t)(blockIdx.x - 8192) * 2048;
#pragma unroll
        for (int j = 0; j < 8; j++) {
            size_t i = base + (size_t)j * 256 + t;
            float4 v = xi[i];
            __half2 h0 = __floats2half2_rn(v.x, v.y);
            __half2 h1 = __floats2half2_rn(v.z, v.w);
            uint2 o;
            o.x = *reinterpret_cast<uint32_t*>(&h0);
            o.y = *reinterpret_cast<uint32_t*>(&h1);
            xo[i] = o;
        }
    }
}

// --- 3) FP16 GEMM: mbarrier pipeline, 2 CTAs/SM, 128 thr, 4 warps of 64x64 ---
// (R13 structure verbatim — best measured configuration.)
#define BM 128
#define BN 128
#define BK 64
#define KCH (KD / BK)              // 64
#define STAGES 3
#define AW 72                      // 64 + 8 pad halfs -> 144B row stride
#define A_HALFS (BM * AW)
#define B_HALFS (BN * AW)
#define STAGE_HALFS (A_HALFS + B_HALFS)        // 18432
#define STAGE_BYTES (STAGE_HALFS * 2)          // 36864
#define MBAR_OFF (STAGES * STAGE_BYTES)        // 110592
#define SMEM_TOTAL (MBAR_OFF + 64)             // 110656 per CTA

__device__ __forceinline__ void cp16(uint32_t saddr, const void* gaddr) {
    asm volatile("cp.async.cg.shared.global [%0], [%1], 16;" :: "r"(saddr), "l"(gaddr));
}
__device__ __forceinline__ void cp_arrive(uint32_t mbar) {
    asm volatile("cp.async.mbarrier.arrive.noinc.shared.b64 [%0];" :: "r"(mbar) : "memory");
}
__device__ __forceinline__ void mbar_init(uint32_t mbar, uint32_t cnt) {
    asm volatile("mbarrier.init.shared.b64 [%0], %1;" :: "r"(mbar), "r"(cnt) : "memory");
}
__device__ __forceinline__ void mbar_arrive(uint32_t mbar) {
    asm volatile("mbarrier.arrive.shared.b64 _, [%0];" :: "r"(mbar) : "memory");
}
__device__ __forceinline__ void mbar_wait(uint32_t mbar, uint32_t par) {
    uint32_t done;
    asm volatile("{\n\t.reg .pred p;\n\t"
                 "mbarrier.try_wait.parity.acquire.cta.shared::cta.b64 p, [%1], %2;\n\t"
                 "selp.b32 %0,1,0,p;\n\t}"
                 : "=r"(done) : "r"(mbar), "r"(par) : "memory");
    if (!done) {
        asm volatile("{\n\t.reg .pred P1;\n\t"
                     "WL_%=:\n\t"
                     "mbarrier.try_wait.parity.acquire.cta.shared::cta.b64 P1, [%0], %1, 0x989680;\n\t"
                     "@P1 bra.uni WD_%=;\n\t"
                     "bra.uni WL_%=;\n\t"
                     "WD_%=:\n\t}"
                     :: "r"(mbar), "r"(par) : "memory");
    }
}
__device__ __forceinline__ void ldsm4(uint32_t& r0, uint32_t& r1, uint32_t& r2, uint32_t& r3,
                                      uint32_t addr) {
    asm volatile("ldmatrix.sync.aligned.m8n8.x4.shared.b16 {%0,%1,%2,%3}, [%4];"
                 : "=r"(r0), "=r"(r1), "=r"(r2), "=r"(r3) : "r"(addr));
}
__device__ __forceinline__ void mma_f16(float* d, const uint32_t* a, const uint32_t* b) {
    asm volatile("mma.sync.aligned.m16n8k16.row.col.f32.f16.f16.f32 "
                 "{%0,%1,%2,%3}, {%4,%5,%6,%7}, {%8,%9}, {%0,%1,%2,%3};"
                 : "+f"(d[0]), "+f"(d[1]), "+f"(d[2]), "+f"(d[3])
                 : "r"(a[0]), "r"(a[1]), "r"(a[2]), "r"(a[3]), "r"(b[0]), "r"(b[1]));
}

__global__ void __launch_bounds__(128, 2) gemm_f16(const float* __restrict__ bias,
                                                   float* __restrict__ out) {
    extern __shared__ __half smh[];
    uint32_t smbase = (uint32_t)__cvta_generic_to_shared(smh);
    uint32_t mbFull  = smbase + MBAR_OFF;        // 3 x 8B
    uint32_t mbEmpty = smbase + MBAR_OFF + 24;   // 3 x 8B
    int tid = threadIdx.x, wid = tid >> 5, lane = tid & 31;
    int wr = wid & 1;            // 2 bs-groups of 64
    int wc = wid >> 1;           // 2 m-groups of 64
    int g = lane >> 2, tig = lane & 3;
    int mBase  = blockIdx.x * BN;
    int bsBase = blockIdx.y * BM;

    if (tid == 0) {
#pragma unroll
        for (int s = 0; s < STAGES; s++) {
            mbar_init(mbFull  + s * 8, 128);
            mbar_init(mbEmpty + s * 8, 128);
        }
    }
    __syncthreads();

    // cp.async staging: srow 0..15, sseg 0..7; rows covered via j*16 (8 groups each)
    int srow = tid >> 3, sseg = tid & 7;
    const __half* gA = g_xh + (size_t)(bsBase + srow) * KD + sseg * 8;
    const __half* gB = g_wh + (size_t)(mBase  + srow) * KD + sseg * 8;
    uint32_t sA0 = smbase + (uint32_t)((srow * AW + sseg * 8) * 2);
    uint32_t sB0 = smbase + (uint32_t)((A_HALFS + srow * AW + sseg * 8) * 2);

#define ISSUE_STAGE(slot, cc)                                                          \
    do {                                                                               \
        uint32_t so = (uint32_t)((slot) * STAGE_BYTES);                                \
        _Pragma("unroll")                                                              \
        for (int j = 0; j < 8; j++)                                                    \
            cp16(sA0 + so + j * 16 * AW * 2, gA + (cc) * BK + (size_t)j * 16 * KD);    \
        _Pragma("unroll")                                                              \
        for (int j = 0; j < 8; j++)                                                    \
            cp16(sB0 + so + j * 16 * AW * 2, gB + (cc) * BK + (size_t)j * 16 * KD);    \
        cp_arrive(mbFull + (slot) * 8);                                                \
    } while (0)

    // prologue: fill stages 0,1 (chunks 0,1)
    ISSUE_STAGE(0, 0);
    ISSUE_STAGE(1, 1);

    // ldmatrix lane addressing
    int li = lane & 7, qq = lane >> 3;
    uint32_t aAddr[4], bAddr[4];
#pragma unroll
    for (int mt = 0; mt < 4; mt++) {
        int row = wr * 64 + mt * 16 + (qq & 1) * 8 + li;
        aAddr[mt] = smbase + (uint32_t)((row * AW + (qq >> 1) * 8) * 2);
    }
#pragma unroll
    for (int p = 0; p < 4; p++) {
        int row = wc * 64 + p * 16 + (qq >> 1) * 8 + li;
        bAddr[p] = smbase + (uint32_t)((A_HALFS + row * AW + (qq & 1) * 8) * 2);
    }

    float acc[4][8][4];
#pragma unroll
    for (int mt = 0; mt < 4; mt++)
#pragma unroll
        for (int nt = 0; nt < 8; nt++)
#pragma unroll
            for (int v = 0; v < 4; v++) acc[mt][nt][v] = 0.0f;

    for (int c = 0; c < KCH; c++) {
        int s = c % STAGES;
        int cd3 = c / STAGES;
        mbar_wait(mbFull + s * 8, (uint32_t)(cd3 & 1));

        uint32_t st = (uint32_t)(s * STAGE_BYTES);
#pragma unroll
        for (int ks = 0; ks < 4; ks++) {
            uint32_t kb = st + ks * 32;          // 16 halfs = 32B
            uint32_t af[4][4], bf[8][2];
#pragma unroll
            for (int mt = 0; mt < 4; mt++)
                ldsm4(af[mt][0], af[mt][1], af[mt][2], af[mt][3], aAddr[mt] + kb);
#pragma unroll
            for (int p = 0; p < 4; p++) {
                uint32_t r0, r1, r2, r3;
                ldsm4(r0, r1, r2, r3, bAddr[p] + kb);
                bf[2 * p][0] = r0;     bf[2 * p][1] = r1;
                bf[2 * p + 1][0] = r2; bf[2 * p + 1][1] = r3;
            }
#pragma unroll
            for (int mt = 0; mt < 4; mt++)
#pragma unroll
                for (int nt = 0; nt < 8; nt++)
                    mma_f16(acc[mt][nt], af[mt], bf[nt]);
        }
        mbar_arrive(mbEmpty + s * 8);

        int c2 = c + 2;
        if (c2 < KCH) {
            int s2 = c2 % STAGES;
            if (c2 >= STAGES)
                mbar_wait(mbEmpty + s2 * 8, (uint32_t)((c2 / STAGES + 1) & 1));
            ISSUE_STAGE(s2, c2);
        }
    }

    // epilogue (no smem use — no barrier needed)
#pragma unroll
    for (int nt = 0; nt < 8; nt++) {
        int col = mBase + wc * 64 + nt * 8 + 2 * tig;
        float2 bv = *reinterpret_cast<const float2*>(bias + col);
#pragma unroll
        for (int mt = 0; mt < 4; mt++) {
            int r0 = bsBase + wr * 64 + mt * 16 + g;
            float2 o0, o1;
            o0.x = acc[mt][nt][0] + bv.x;
            o0.y = acc[mt][nt][1] + bv.y;
            o1.x = acc[mt][nt][2] + bv.x;
            o1.y = acc[mt][nt][3] + bv.y;
            *reinterpret_cast<float2*>(out + (size_t)r0 * MD + col) = o0;
            *reinterpret_cast<float2*>(out + (size_t)(r0 + 8) * MD + col) = o1;
        }
    }
}

// ---------------- launch ----------------
extern "C" void kernel_launch(void* const* d_in, const int* in_sizes, int n_in,
                              void* d_out, int out_size) {
    const float* x    = (const float*)d_in[0];
    const float* dna  = (const float*)d_in[1];
    const float* bias = (const float*)d_in[2];
    const int*   hd   = (const int*)d_in[3];

    lut_kernel<<<(NLUT + 1 + 255) / 256, 256>>>(dna);
    stat_kernel<<<64, 256>>>();
    prep_kernel<<<12288, 256>>>(hd, x);

    cudaFuncSetAttribute(gemm_f16, cudaFuncAttributeMaxDynamicSharedMemorySize, SMEM_TOTAL);
    dim3 grid(MD / BN, BSD / BM);   // (32, 64), m-fastest
    gemm_f16<<<grid, 128, SMEM_TOTAL>>>(bias, (float*)d_out);
}